// round 17
// baseline (speedup 1.0000x reference)
#include <cuda_runtime.h>
#include <cuda_bf16.h>
#include <cuda_fp16.h>
#include <math.h>
#include <stdint.h>

// ---------------- problem constants ----------------
#define S_LEN 2048
#define BATCH 2
#define NTOK  (S_LEN*BATCH)     // 4096
#define NH    16
#define DIM   2048
#define NOPE  128
#define ROPE  64
#define RHALF 32
#define VDIM  128
#define KVR   512
#define QD    (NOPE+ROPE)       // 192
#define QOUT  (NH*QD)           // 3072
#define KVOUT (KVR+ROPE)        // 576
#define KVPAD 640               // kv-proj N padded to 5*128
#define DEFF  576
#define LOG2E 1.4426950408889634

typedef long long ll;
typedef __nv_bfloat16 bf16;
typedef __nv_bfloat162 bf162;

// ---------------- scratch ----------------
__device__ __align__(16) half g_xs_f [(size_t)NTOK*DIM];
__device__ __align__(16) half g_wqf  [(size_t)QOUT*DIM];
__device__ __align__(16) half g_waf_h[(size_t)KVPAD*DIM], g_waf_l[(size_t)KVPAD*DIM];
__device__ __align__(16) half g_wbv  [(size_t)NH*VDIM*KVR];
__device__ __align__(16) half g_wbTf_h[(size_t)NH*KVR*NOPE], g_wbTf_l[(size_t)NH*KVR*NOPE];
__device__ __align__(16) half g_wof  [(size_t)DIM*NH*VDIM];
__device__ __align__(16) half g_qs_f [(size_t)NTOK*QOUT];
__device__ __align__(16) bf16 g_kvs_h[(size_t)NTOK*KVPAD],  g_kvs_l[(size_t)NTOK*KVPAD];
__device__ __align__(16) half g_ke  [(size_t)NTOK*DEFF];
__device__ __align__(16) half g_keT [(size_t)BATCH*DEFF*S_LEN];
__device__ __align__(16) half g_qe  [(size_t)BATCH*NH*S_LEN*DEFF];
__device__ float g_scores[(size_t)BATCH*NH*S_LEN*S_LEN];
__device__ __align__(16) half g_pr   [(size_t)BATCH*NH*S_LEN*S_LEN];
__device__ __align__(16) half g_ol   [(size_t)BATCH*NH*S_LEN*KVR];
__device__ __align__(16) half g_os   [(size_t)NTOK*NH*VDIM];
__device__ float g_cos[S_LEN*RHALF];
__device__ float g_sin[S_LEN*RHALF];

// ---------------- helpers ----------------
__device__ __forceinline__ float warpMax(float v){
    #pragma unroll
    for (int o=16;o;o>>=1) v = fmaxf(v, __shfl_xor_sync(0xffffffffu, v, o));
    return v;
}
__device__ __forceinline__ float warpSum(float v){
    #pragma unroll
    for (int o=16;o;o>>=1) v += __shfl_xor_sync(0xffffffffu, v, o);
    return v;
}
__device__ __forceinline__ uint32_t smem_u32(const void* p){
    uint32_t a;
    asm("{ .reg .u64 t; cvta.to.shared.u64 t, %1; cvt.u32.u64 %0, t; }" : "=r"(a) : "l"(p));
    return a;
}
__device__ __forceinline__ void split2(float f, bf16& h, bf16& l){
    h = __float2bfloat16_rn(f);
    l = __float2bfloat16_rn(f - __bfloat162float(h));
}
__device__ __forceinline__ void split2h(float f, half& h, half& l){
    h = __float2half_rn(f);
    l = __float2half_rn(f - __half2float(h));
}
__device__ __forceinline__ float rejoin(bf16 h, bf16 l){
    return __bfloat162float(h) + __bfloat162float(l);
}
__device__ __forceinline__ void mma_f16(float* d, const uint32_t* a, const uint32_t* b){
    asm volatile(
        "mma.sync.aligned.m16n8k16.row.col.f32.f16.f16.f32 "
        "{%0,%1,%2,%3}, {%4,%5,%6,%7}, {%8,%9}, {%0,%1,%2,%3};"
        : "+f"(d[0]), "+f"(d[1]), "+f"(d[2]), "+f"(d[3])
        : "r"(a[0]), "r"(a[1]), "r"(a[2]), "r"(a[3]), "r"(b[0]), "r"(b[1]));
}
__device__ __forceinline__ void ldsm4(uint32_t* r, uint32_t a){
    asm volatile("ldmatrix.sync.aligned.m8n8.x4.shared.b16 {%0,%1,%2,%3}, [%4];"
        : "=r"(r[0]), "=r"(r[1]), "=r"(r[2]), "=r"(r[3]) : "r"(a));
}
__device__ __forceinline__ void cp16(uint32_t dst, const void* src){
    asm volatile("cp.async.cg.shared.global [%0], [%1], 16;\n" :: "r"(dst), "l"(src) : "memory");
}
__device__ __forceinline__ void cp_commit(){ asm volatile("cp.async.commit_group;\n" ::: "memory"); }
template<int N>
__device__ __forceinline__ void cp_wait(){ asm volatile("cp.async.wait_group %0;\n" :: "n"(N) : "memory"); }

__device__ __forceinline__ uint32_t swz(uint32_t o){ return o ^ ((o>>3)&0x30u); }

// ---------------- fused convert/split/rope kernel ----------------
#define N4_X   (NTOK*DIM/4)
#define N4_WQ  (QOUT*DIM/4)
#define N4_WA  (KVPAD*DIM/4)
#define N4_WAV (KVOUT*DIM/4)
#define N4_WBV (NH*VDIM*KVR/4)
#define N4_WO  (DIM*NH*VDIM/4)
#define N_WBT  (NH*KVR*NOPE)
#define N_ROPE (S_LEN*RHALF)
#define N_CONV (N4_X + N4_WQ + N4_WA + N4_WBV + N4_WO + N_WBT + N_ROPE)

__global__ void mega_convert(const float4* __restrict__ x, const float4* __restrict__ wq,
                             const float4* __restrict__ wkv_a, const float* __restrict__ wkv_b,
                             const float4* __restrict__ wo, const float* __restrict__ ang)
{
    int idx = blockIdx.x*256 + threadIdx.x;
    if (idx < N4_X){
        float4 v = x[idx];
        __half2* dp = (__half2*)(g_xs_f + 4*(size_t)idx);
        __half2 a; a.x=__float2half_rn(v.x); a.y=__float2half_rn(v.y); dp[0]=a;
        __half2 b; b.x=__float2half_rn(v.z); b.y=__float2half_rn(v.w); dp[1]=b;
        return;
    }
    idx -= N4_X;
    if (idx < N4_WQ){
        float4 v = wq[idx];
        __half2* dp = (__half2*)(g_wqf + 4*(size_t)idx);
        __half2 a; a.x=__float2half_rn(v.x); a.y=__float2half_rn(v.y); dp[0]=a;
        __half2 b; b.x=__float2half_rn(v.z); b.y=__float2half_rn(v.w); dp[1]=b;
        return;
    }
    idx -= N4_WQ;
    if (idx < N4_WA){
        __half2 a,b,c,d;
        if (idx < N4_WAV){
            float4 v = wkv_a[idx];
            half h0,l0,h1,l1,h2,l2,h3,l3;
            split2h(v.x,h0,l0); split2h(v.y,h1,l1); split2h(v.z,h2,l2); split2h(v.w,h3,l3);
            a.x=h0; a.y=h1; b.x=h2; b.y=h3; c.x=l0; c.y=l1; d.x=l2; d.y=l3;
        } else {
            half z = __float2half_rn(0.f);
            a.x=z; a.y=z; b=a; c=a; d=a;
        }
        __half2* hp = (__half2*)(g_waf_h + 4*(size_t)idx);
        __half2* lp = (__half2*)(g_waf_l + 4*(size_t)idx);
        hp[0]=a; hp[1]=b; lp[0]=c; lp[1]=d;
        return;
    }
    idx -= N4_WA;
    if (idx < N4_WBV){
        int e = idx*4;
        int c = e % KVR, v = (e/KVR) % VDIM, h = e/(KVR*VDIM);
        const float4* src = (const float4*)(wkv_b + ((size_t)h*(NOPE+VDIM) + NOPE + v)*KVR + c);
        float4 w = src[0];
        __half2* dp = (__half2*)(g_wbv + 4*(size_t)idx);
        __half2 a; a.x=__float2half_rn(w.x); a.y=__float2half_rn(w.y); dp[0]=a;
        __half2 b; b.x=__float2half_rn(w.z); b.y=__float2half_rn(w.w); dp[1]=b;
        return;
    }
    idx -= N4_WBV;
    if (idx < N4_WO){
        float4 v = wo[idx];
        __half2* dp = (__half2*)(g_wof + 4*(size_t)idx);
        __half2 a; a.x=__float2half_rn(v.x); a.y=__float2half_rn(v.y); dp[0]=a;
        __half2 b; b.x=__float2half_rn(v.z); b.y=__float2half_rn(v.w); dp[1]=b;
        return;
    }
    idx -= N4_WO;
    if (idx < N_WBT){
        int d = idx % NOPE, c = (idx/NOPE) % KVR, h = idx/(NOPE*KVR);
        float v = wkv_b[((size_t)h*(NOPE+VDIM) + d)*KVR + c];
        split2h(v, g_wbTf_h[idx], g_wbTf_l[idx]);
        return;
    }
    idx -= N_WBT;
    if (idx < N_ROPE){
        float a = ang[idx];
        g_cos[idx] = cosf(a);
        g_sin[idx] = sinf(a);
    }
}

// ---------------- prep kernels ----------------
__global__ void prep_keff_kernel(const float* __restrict__ kvw){
    int t = blockIdx.x;
    int s = t % S_LEN;
    int tid = threadIdx.x;
    float v[4];
    #pragma unroll
    for (int j=0;j<4;j++){
        size_t idx = (size_t)t*KVPAD + 4*tid + j;
        v[j] = rejoin(g_kvs_h[idx], g_kvs_l[idx]);
    }
    float ss = v[0]*v[0]+v[1]*v[1]+v[2]*v[2]+v[3]*v[3];
    ss = warpSum(ss);
    __shared__ float red[4];
    if ((tid&31)==0) red[tid>>5] = ss;
    __syncthreads();
    float tot = red[0]+red[1]+red[2]+red[3];
    float r = rsqrtf(tot*(1.0f/KVR) + 1e-6f);
    #pragma unroll
    for (int j=0;j<4;j++){
        int c = 4*tid + j;
        g_ke[(size_t)t*DEFF + c] = __float2half_rn(v[j]*r*kvw[c]);
    }
    if (tid < RHALF){
        size_t pi = (size_t)t*KVPAD + KVR + 2*tid;
        float xr = rejoin(g_kvs_h[pi],   g_kvs_l[pi]);
        float xi = rejoin(g_kvs_h[pi+1], g_kvs_l[pi+1]);
        float c  = g_cos[s*RHALF+tid], sn = g_sin[s*RHALF+tid];
        size_t di = (size_t)t*DEFF + KVR + 2*tid;
        g_ke[di]   = __float2half_rn(xr*c - xi*sn);
        g_ke[di+1] = __float2half_rn(xr*sn + xi*c);
    }
}

// coalesced tiled transpose: ke (fp16, [tok][DEFF]) -> keT (fp16, [b][DEFF][S])
__global__ void transpose_keT(){
    __shared__ half th[32][33];
    int b = blockIdx.z;
    int c0 = blockIdx.y*32, s0 = blockIdx.x*32;
    int tx = threadIdx.x, ty = threadIdx.y;   // 32 x 8
    #pragma unroll
    for (int i=0;i<32;i+=8){
        th[ty+i][tx] = g_ke[(size_t)(b*S_LEN + s0 + ty + i)*DEFF + c0 + tx];
    }
    __syncthreads();
    #pragma unroll
    for (int i=0;i<32;i+=8){
        g_keT[((size_t)b*DEFF + c0 + ty + i)*S_LEN + s0 + tx] = th[tx][ty+i];
    }
}

// one block per token, 512 threads = 16 heads x 32 rope pairs; q stored fp16
__global__ void prep_qpe_kernel(){
    int t = blockIdx.x;
    int b = t / S_LEN, s = t % S_LEN;
    int h = threadIdx.x >> 5, i = threadIdx.x & 31;
    size_t si = (size_t)t*QOUT + h*QD + NOPE + 2*i;
    float xr = __half2float(g_qs_f[si]);
    float xi = __half2float(g_qs_f[si+1]);
    float c  = g_cos[s*RHALF+i], sn = g_sin[s*RHALF+i];
    size_t di = ((size_t)(b*NH+h)*S_LEN + s)*DEFF + KVR + 2*i;
    g_qe[di]   = __float2half_rn(xr*c - xi*sn);
    g_qe[di+1] = __float2half_rn(xr*sn + xi*c);
}

// ---------------- split GEMM with ldmatrix ----------------
// MODE 1: fp16 2p (A single fp16, B hi/lo fp16, 2 passes, 4 stages)
// MODE 2: fp16 1p (A single fp16, B single fp16, 1 pass, 6 stages)
// OUT: 0 = fp32, 1 = bf16 hi/lo planes, 2 = single fp16 plane.
// klimit also reverses the by mapping so long-K blocks start first.
// INVARIANT: prologue always commits exactly NST-1 groups (empty commits when nk < NST-1),
// so cp_wait<NST-2> is guaranteed to retire the oldest stage.
template<int BN_T, int OUT, int MODE>
__global__ __launch_bounds__(256,2) void mma_gemm(
    const bf16* __restrict__ Ah, const bf16* __restrict__ Al,
    const bf16* __restrict__ Bh, const bf16* __restrict__ Bl,
    float* __restrict__ Cf, bf16* __restrict__ Ch, bf16* __restrict__ Cl,
    int K, int lda, int ldb, int ldc, int zdiv,
    ll zA1, ll zA2, ll zB1, ll zB2, ll zC1, ll zC2,
    float alpha, int causal, int klimit)
{
    const int byy = klimit ? ((int)gridDim.y - 1 - (int)blockIdx.y) : (int)blockIdx.y;
    if (causal && (int)blockIdx.x > byy) return;
    constexpr int NST = (MODE==2) ? 6 : 4;
    constexpr int NPA = 1;
    constexpr int NPB = (MODE==2) ? 1 : 2;
    constexpr int WN  = BN_T/32;
    constexpr int WM  = 8/WN;
    constexpr int WTM = 128/WM;
    constexpr int MF  = WTM/16;
    constexpr int NF  = 4;
    constexpr int SA  = 128*64;
    constexpr int SB  = BN_T*64;
    constexpr int STG = NPA*SA + NPB*SB;

    extern __shared__ char smc[];
    const uint32_t sbase = smem_u32(smc);

    const int tid = threadIdx.x, lane = tid & 31, wid = tid >> 5;
    const int wm = wid / WN, wn = wid % WN;
    const int grp = lane >> 2, tig = lane & 3;
    const int lrow = lane & 7, sub = lane >> 3;
    const int zl = blockIdx.z % zdiv, zh = blockIdx.z / zdiv;
    const ll n0 = (ll)blockIdx.x * BN_T;

    const int aRowB = wm*WTM + ((sub&1)<<3) + lrow;
    const int aKo   = (sub>>1)<<4;
    const int bRowB = wn*32 + ((sub>>1)<<3) + lrow;
    const int bKo   = (sub&1)<<4;

    const ll aoff = zl*zA1 + zh*zA2 + (ll)byy*128*lda;
    const bf16* Ahb = Ah + aoff;
    const ll boff = zl*zB1 + zh*zB2 + n0*ldb;
    const bf16* Bhb = Bh + boff;
    const bf16* Blb = Bl + boff;

    int kEnd = K;
    if (klimit){ int kl = (byy + 1)*128; if (kl < kEnd) kEnd = kl; }
    const int nk = kEnd >> 5;

    float acc[MF][NF][4];
    #pragma unroll
    for (int i=0;i<MF;i++)
        #pragma unroll
        for (int j=0;j<NF;j++)
            #pragma unroll
            for (int c=0;c<4;c++) acc[i][j][c] = 0.f;

    const int row = tid >> 2, g = tid & 3;

    auto LOAD = [&](int kb){
        const int s = kb % NST;
        const uint32_t ub = sbase + (uint32_t)(s*STG);
        const ll koff = ((ll)kb << 5) + g*8;
        #pragma unroll
        for (int i=0;i<2;i++){
            int r = row + i*64;
            uint32_t o = swz((uint32_t)(r*64 + g*16));
            cp16(ub + o, Ahb + (ll)r*lda + koff);
        }
        const uint32_t bb = ub + NPA*SA;
        #pragma unroll
        for (int i=0;i<BN_T/64;i++){
            int r = row + i*64;
            uint32_t o = swz((uint32_t)(r*64 + g*16));
            cp16(bb + o, Bhb + (ll)r*ldb + koff);
            if (MODE!=2) cp16(bb + SB + o, Blb + (ll)r*ldb + koff);
        }
        cp_commit();
    };

    #pragma unroll
    for (int kb=0; kb<NST-1; kb++){
        if (kb < nk) LOAD(kb);
        else cp_commit();               // keep group count = NST-1 regardless of nk
    }

    for (int k=0; k<nk; k++){
        cp_wait<NST-2>();
        __syncthreads();
        if (k + NST - 1 < nk) LOAD(k + NST - 1);
        else cp_commit();
        const int s = k % NST;
        const uint32_t AH = sbase + (uint32_t)(s*STG);
        const uint32_t BH = AH + NPA*SA;
        const uint32_t BL = BH + SB;

        #pragma unroll
        for (int kk=0; kk<2; kk++){
            const int ck = kk*32;
            uint32_t bh[2*NF], bl[2*NF];
            #pragma unroll
            for (int nfp=0; nfp<NF/2; nfp++){
                uint32_t bo = swz((uint32_t)((bRowB + nfp*16)*64 + ck + bKo));
                ldsm4(&bh[4*nfp], BH + bo);
                if (MODE!=2) ldsm4(&bl[4*nfp], BL + bo);
            }
            #pragma unroll
            for (int mf=0; mf<MF; mf++){
                uint32_t ao = swz((uint32_t)((aRowB + mf*16)*64 + ck + aKo));
                uint32_t ah[4];
                ldsm4(ah, AH + ao);
                #pragma unroll
                for (int nf=0; nf<NF; nf++) mma_f16(acc[mf][nf], ah, &bh[2*nf]);
                if (MODE==1){
                    #pragma unroll
                    for (int nf=0; nf<NF; nf++) mma_f16(acc[mf][nf], ah, &bl[2*nf]);
                }
            }
        }
    }

    // ---- epilogue ----
    const ll cbase = zl*zC1 + zh*zC2
                   + ((ll)byy*128 + wm*WTM)*ldc + n0 + wn*32;
    #pragma unroll
    for (int mf=0; mf<MF; mf++){
        int r0 = mf*16 + grp;
        #pragma unroll
        for (int nf=0; nf<NF; nf++){
            int c = nf*8 + tig*2;
            #pragma unroll
            for (int half_=0; half_<2; half_++){
                ll off = cbase + (ll)(r0 + half_*8)*ldc + c;
                float v0 = acc[mf][nf][2*half_+0]*alpha;
                float v1 = acc[mf][nf][2*half_+1]*alpha;
                if (OUT == 1){
                    bf16 h0,l0,h1,l1;
                    split2(v0,h0,l0); split2(v1,h1,l1);
                    bf162 hp; hp.x=h0; hp.y=h1;
                    bf162 lp; lp.x=l0; lp.y=l1;
                    *(bf162*)(Ch + off) = hp;
                    *(bf162*)(Cl + off) = lp;
                } else if (OUT == 2){
                    __half2 hp;
                    hp.x = __float2half_rn(v0);
                    hp.y = __float2half_rn(v1);
                    *(__half2*)((half*)Ch + off) = hp;
                } else {
                    float2 o; o.x=v0; o.y=v1;
                    *(float2*)(Cf + off) = o;
                }
            }
        }
    }
}

// ---------------- causal softmax (vectorized, 256 thr) -> single fp16 probs ----------------
__global__ void softmax_kernel(){
    const int s = blockIdx.x;
    const ll z = blockIdx.y;
    const float* row = g_scores + (z*S_LEN + (ll)s)*S_LEN;
    half* pr = g_pr + (z*S_LEN + (ll)s)*S_LEN;
    const int n = s + 1;
    const int nend = ((s>>7)+1)<<7;
    const int tid = threadIdx.x;

    float e[8];
    float mx = -1e30f;
    #pragma unroll
    for (int i=0;i<2;i++){
        int t4 = tid*4 + i*1024;
        if (t4 < n){
            float4 v = *(const float4*)(row + t4);   // [n, nend) is valid memory (computed, masked later)
            e[4*i+0] = v.x;
            e[4*i+1] = (t4+1 < n) ? v.y : -1e30f;
            e[4*i+2] = (t4+2 < n) ? v.z : -1e30f;
            e[4*i+3] = (t4+3 < n) ? v.w : -1e30f;
        } else {
            e[4*i+0]=e[4*i+1]=e[4*i+2]=e[4*i+3] = -1e30f;
        }
        mx = fmaxf(mx, fmaxf(fmaxf(e[4*i],e[4*i+1]), fmaxf(e[4*i+2],e[4*i+3])));
    }
    mx = warpMax(mx);
    __shared__ float redm[8], reds[8];
    if ((tid&31)==0) redm[tid>>5] = mx;
    __syncthreads();
    #pragma unroll
    for (int w=0; w<8; w++) mx = fmaxf(mx, redm[w]);

    float sum = 0.f;
    #pragma unroll
    for (int i=0;i<8;i++){
        float v = (e[i] > -1e29f) ? exp2f(e[i] - mx) : 0.f;
        e[i] = v;
        sum += v;
    }
    sum = warpSum(sum);
    if ((tid&31)==0) reds[tid>>5] = sum;
    __syncthreads();
    sum = 0.f;
    #pragma unroll
    for (int w=0; w<8; w++) sum += reds[w];
    const float inv = 1.0f / sum;

    #pragma unroll
    for (int i=0;i<2;i++){
        int t4 = tid*4 + i*1024;
        if (t4 < nend){
            __half2 a, b;
            a.x = __float2half_rn(e[4*i+0]*inv);
            a.y = __float2half_rn(e[4*i+1]*inv);
            b.x = __float2half_rn(e[4*i+2]*inv);
            b.y = __float2half_rn(e[4*i+3]*inv);
            *(__half2*)(pr + t4)     = a;
            *(__half2*)(pr + t4 + 2) = b;
        }
    }
}

// ---------------- host side ----------------
// omode: 0 fp32, 1 bf16 hi/lo, 2 fp16 single ; mode: 1 fp16-2p, 2 fp16-1p
static void launch_g(int omode, int mode,
    const bf16* Ah, const bf16* Al, const bf16* Bh, const bf16* Bl,
    float* Cf, bf16* Ch, bf16* Cl,
    int M, int N, int K, int lda, int ldb, int ldc,
    int Z, int zdiv,
    ll zA1, ll zA2, ll zB1, ll zB2, ll zC1, ll zC2,
    float alpha, bool causal, bool klimit)
{
    dim3 grid(N/128, M/128, Z);
    int c = causal?1:0, kl = klimit?1:0;
    #define GO(O,M_) { \
        size_t sm = (size_t)((M_==2)?6:4) * ((1 + ((M_==2)?1:2))*128*64); \
        cudaFuncSetAttribute(mma_gemm<128,O,M_>, cudaFuncAttributeMaxDynamicSharedMemorySize, (int)sm); \
        mma_gemm<128,O,M_><<<grid,256,sm>>>(Ah,Al,Bh,Bl,Cf,Ch,Cl,K,lda,ldb,ldc,zdiv,zA1,zA2,zB1,zB2,zC1,zC2,alpha,c,kl); \
        return; }
    if (mode==1 && omode==1) GO(1,1);
    if (mode==1 && omode==2) GO(2,1);
    if (mode==2 && omode==0) GO(0,2);
    if (mode==2 && omode==2) GO(2,2);
    #undef GO
}

#define SYM(p, s) cudaGetSymbolAddress((void**)&p, s)

extern "C" void kernel_launch(void* const* d_in, const int* in_sizes, int n_in,
                              void* d_out, int out_size)
{
    (void)in_sizes; (void)n_in; (void)out_size;
    const float* x      = (const float*)d_in[0];
    const float* angles = (const float*)d_in[1];
    const float* wq     = (const float*)d_in[2];
    const float* wkv_a  = (const float*)d_in[3];
    const float* wkv_b  = (const float*)d_in[4];
    const float* wo     = (const float*)d_in[5];
    const float* kvw    = (const float*)d_in[6];
    float* out = (float*)d_out;

    bf16 *kvh,*kvl;
    half *xsf,*wqf,*wafh,*wafl,*wbv,*wbTfh,*wbTfl,*wof;
    half *qsf,*ke,*keT,*qe,*pr,*ol,*os;
    float *sc;
    SYM(xsf,g_xs_f); SYM(wqf,g_wqf);
    SYM(wafh,g_waf_h); SYM(wafl,g_waf_l); SYM(wbv,g_wbv);
    SYM(wbTfh,g_wbTf_h); SYM(wbTfl,g_wbTf_l); SYM(wof,g_wof);
    SYM(qsf,g_qs_f); SYM(kvh,g_kvs_h); SYM(kvl,g_kvs_l);
    SYM(ke,g_ke); SYM(keT,g_keT);
    SYM(qe,g_qe); SYM(pr,g_pr);
    SYM(ol,g_ol); SYM(os,g_os);
    SYM(sc,g_scores);

    const double msc = 0.1*log(40.0) + 1.0;
    const float softmax_scale = (float)(pow((double)QD, -0.5)*msc*msc);
    const float score_alpha = (float)((double)softmax_scale * LOG2E);

    // 0) ONE fused convert/split/rope kernel
    mega_convert<<<(N_CONV+255)/256, 256>>>(
        (const float4*)x, (const float4*)wq, (const float4*)wkv_a, wkv_b, (const float4*)wo, angles);

    // 1) q = x(fp16) @ wq(fp16)^T  (1-pass -> fp16 single)
    launch_g(2,2, (const bf16*)xsf, 0, (const bf16*)wqf, 0, 0, (bf16*)qsf, 0,
             NTOK, QOUT, DIM, DIM, DIM, QOUT, 1,1, 0,0,0,0,0,0, 1.f,false,false);

    // 2) kv = x(fp16) @ wkv_a(fp16 hi/lo)^T  (2-pass -> bf16 hi/lo, N padded to 640)
    launch_g(1,1, (const bf16*)xsf, 0, (const bf16*)wafh, (const bf16*)wafl, 0, kvh,kvl,
             NTOK, KVPAD, DIM, DIM, DIM, KVPAD, 1,1, 0,0,0,0,0,0, 1.f,false,false);

    // 3) keff (single fp16) + keT transpose
    prep_keff_kernel<<<NTOK, 128>>>(kvw);
    transpose_keT<<<dim3(S_LEN/32, DEFF/32, BATCH), dim3(32,8)>>>();

    // 4) rope(q_pe) -> qe fp16
    prep_qpe_kernel<<<NTOK, 512>>>();

    // 5) qe[...,0:512] = q_nope(fp16) @ wbT(fp16 hi/lo)  (2-pass -> fp16 single)
    launch_g(2,1, (const bf16*)qsf, 0, (const bf16*)wbTfh, (const bf16*)wbTfl, 0, (bf16*)qe, 0,
             S_LEN, KVR, NOPE, QOUT, NOPE, DEFF, BATCH*NH, NH,
             (ll)QD, (ll)S_LEN*QOUT, (ll)KVR*NOPE, 0,
             (ll)S_LEN*DEFF, (ll)NH*S_LEN*DEFF, 1.f,false,false);

    // 6) scores = scale * qe(fp16) @ ke(fp16)^T  (1-pass, causal block-skip)
    launch_g(0,2, (const bf16*)qe, 0, (const bf16*)ke, 0, sc, 0,0,
             S_LEN, S_LEN, DEFF, DEFF, DEFF, S_LEN, BATCH*NH, NH,
             (ll)S_LEN*DEFF, (ll)NH*S_LEN*DEFF, 0, (ll)S_LEN*DEFF,
             (ll)S_LEN*S_LEN, (ll)NH*S_LEN*S_LEN, score_alpha, true, false);

    // 7) softmax -> fp16 probs (vectorized, 256 thr)
    softmax_kernel<<<dim3(S_LEN, BATCH*NH), 256>>>();

    // 8) olat = probs(fp16) @ keT(fp16)^T -> fp16, 1-pass, K capped, long-K-first
    launch_g(2,2, (const bf16*)pr, 0, (const bf16*)keT, 0, 0, (bf16*)ol, 0,
             S_LEN, KVR, S_LEN, S_LEN, S_LEN, KVR, BATCH*NH, NH,
             (ll)S_LEN*S_LEN, (ll)NH*S_LEN*S_LEN, 0, (ll)DEFF*S_LEN,
             (ll)S_LEN*KVR, (ll)NH*S_LEN*KVR, 1.f, false, true);

    // 9) o = olat(fp16) @ wbv(fp16)^T -> fp16, 1-pass (per (b,h), K=512)
    launch_g(2,2, (const bf16*)ol, 0, (const bf16*)wbv, 0, 0, (bf16*)os, 0,
             S_LEN, VDIM, KVR, KVR, KVR, NH*VDIM, BATCH*NH, NH,
             (ll)S_LEN*KVR, (ll)NH*S_LEN*KVR, (ll)VDIM*KVR, 0,
             (ll)VDIM, (ll)S_LEN*NH*VDIM, 1.f, false, false);

    // 10) out = o(fp16) @ wo(fp16)^T -> fp32, 1-pass
    launch_g(0,2, (const bf16*)os, 0, (const bf16*)wof, 0, out, 0,0,
             NTOK, DIM, NH*VDIM, NH*VDIM, NH*VDIM, DIM, 1,1,
             0,0,0,0,0,0, 1.f,false,false);
}